// round 7
// baseline (speedup 1.0000x reference)
#include <cuda_runtime.h>

// SideWindowFilter: 24 planes of 768x768 fp32, r=2, 3 iterations.
// Per pixel: 6 box sums -> 8 directional means -> argmin |mean - x| -> x += d.
// Rolling vertical 3-row sums exploit S_bl(s)=S_tl(s+2), S_bot(s)=S_top(s+2);
// shared loads are software-pipelined one full step ahead.

#define HH 768
#define WW 768
#define NPLANES 24
#define TW 64          // tile width
#define TH 64          // tile height
#define RPT 16         // rows per thread; block = (32,4) = 128 threads
#define XS 68          // tile + 2*2 halo

typedef unsigned long long u64;

__device__ float g_scratch[NPLANES * HH * WW];

__device__ __forceinline__ u64 pk(float lo, float hi) {
    u64 r; asm("mov.b64 %0, {%1, %2};" : "=l"(r) : "f"(lo), "f"(hi)); return r;
}
__device__ __forceinline__ u64 fadd2(u64 a, u64 b) {
    u64 r; asm("add.rn.f32x2 %0, %1, %2;" : "=l"(r) : "l"(a), "l"(b)); return r;
}
__device__ __forceinline__ u64 ffma2(u64 a, u64 b, u64 c) {
    u64 r; asm("fma.rn.f32x2 %0, %1, %2, %3;" : "=l"(r) : "l"(a), "l"(b), "l"(c)); return r;
}
__device__ __forceinline__ float2 asf2(u64 v) {
    union { u64 u; float2 f; } cv; cv.u = v; return cv.f;
}
__device__ __forceinline__ u64 asu64(float2 f) {
    union { float2 f; u64 u; } cv; cv.f = f; return cv.u;
}

// Load one row's three float2s (6 floats, 3 LDS.64).
#define PREFETCH(rr) do {                                               \
    const float2* f2r = (const float2*)xs[rr];                          \
    q0 = f2r[tx]; q1 = f2r[tx + 1]; q2 = f2r[tx + 2];                   \
} while (0)

// Horizontal sums from prefetched q registers (5 packed adds, no loads).
//   A = {x0+x1+x2, x1+x2+x3}   B = {x2+x3+x4, x3+x4+x5}
//   F = {x0..x4,   x1..x5}     C = {x2, x3}
#define BUILDQ(A, B, F, C) do {                                         \
    const u64 P0 = asu64(q0), P1 = asu64(q1), P2 = asu64(q2);           \
    const u64 s01 = pk(q0.y, q1.x);                                     \
    const u64 s23 = pk(q1.y, q2.x);                                     \
    const u64 t   = fadd2(s23, P2);                                     \
    A = fadd2(fadd2(P0, s01), P1);                                      \
    B = fadd2(P1, t);                                                   \
    F = fadd2(A, t);                                                    \
    C = P1;                                                             \
} while (0)

__global__ __launch_bounds__(128)
void swf_step(const float* __restrict__ in_ext, float* __restrict__ out_ext,
              int in_is_scratch, int out_is_scratch)
{
    __shared__ float xs[XS][XS];   // 18.5 KB

    const float* __restrict__ in  = in_is_scratch  ? (const float*)g_scratch : in_ext;
    float* __restrict__       out = out_is_scratch ? (float*)g_scratch       : out_ext;

    const int plane = blockIdx.z;
    const int gx0 = blockIdx.x * TW;
    const int gy0 = blockIdx.y * TH;
    const float* __restrict__ pin = in  + (size_t)plane * HH * WW;
    float* __restrict__ pout      = out + (size_t)plane * HH * WW;

    const int tx = threadIdx.x;      // 0..31 -> col pair 2*tx
    const int ty = threadIdx.y;      // 0..3  -> row group of 16

    // ---- Phase 1: load 68x68 tile (+halo) ----
    const bool interior = (gx0 >= 2) & (gx0 + XS - 2 <= WW) &
                          (gy0 >= 2) & (gy0 + XS - 2 <= HH);
    if (interior) {
        const float* src0 = pin + (size_t)(gy0 - 2) * WW + (gx0 - 2);
        #pragma unroll
        for (int r = ty; r < XS; r += 4) {
            const float* src = src0 + (size_t)r * WW;
            xs[r][tx]      = __ldg(&src[tx]);
            xs[r][tx + 32] = __ldg(&src[tx + 32]);
            if (tx < XS - TW) xs[r][tx + 64] = __ldg(&src[tx + 64]);
        }
    } else {
        #pragma unroll
        for (int r = ty; r < XS; r += 4) {
            const int gy = gy0 - 2 + r;
            const bool yok = (unsigned)gy < HH;
            const int gxa = gx0 - 2 + tx;
            float v0 = 0.0f, v1 = 0.0f;
            if (yok && (unsigned)gxa < WW)        v0 = __ldg(&pin[(size_t)gy * WW + gxa]);
            xs[r][tx] = v0;
            if (yok && (unsigned)(gxa + 32) < WW) v1 = __ldg(&pin[(size_t)gy * WW + gxa + 32]);
            xs[r][tx + 32] = v1;
            if (tx < XS - TW) {
                float v2 = 0.0f;
                if (yok && (unsigned)(gxa + 64) < WW) v2 = __ldg(&pin[(size_t)gy * WW + gxa + 64]);
                xs[r][tx + 64] = v2;
            }
        }
    }
    __syncthreads();

    const u64 K15 = pk(1.0f / 15.0f, 1.0f / 15.0f);
    const u64 K9  = pk(1.0f / 9.0f,  1.0f / 9.0f);
    const u64 K81 = pk(1.0f / 81.0f, 1.0f / 81.0f);

    const int r0 = ty * RPT;

    float2 q0, q1, q2;

    // ---- Warm-up: rows r0..r0+4 -> rings ----
    u64 TA0, TA1, TA2, TB0, TB1, TB2, TF0, TF1, TF2;  // vertical 3-row sums
    u64 A3, A4, B3, B4, F3, F4;                       // last two rows' h-sums
    u64 C2, C3, C4;                                   // centers (rows s+2..s+4)
    {
        u64 Aa, Ab, Ac, Ba, Bb, Bc, Fa, Fb, Fc, Cd;
        PREFETCH(r0 + 0); BUILDQ(Aa, Ba, Fa, Cd);
        PREFETCH(r0 + 1); BUILDQ(Ab, Bb, Fb, Cd);
        PREFETCH(r0 + 2); BUILDQ(Ac, Bc, Fc, C2);
        PREFETCH(r0 + 3); BUILDQ(A3, B3, F3, C3);
        PREFETCH(r0 + 4); BUILDQ(A4, B4, F4, C4);
        (void)Cd;
        TA0 = fadd2(fadd2(Aa, Ab), Ac);
        TA1 = fadd2(fadd2(Ab, Ac), A3);
        TA2 = fadd2(fadd2(Ac, A3), A4);
        TB0 = fadd2(fadd2(Ba, Bb), Bc);
        TB1 = fadd2(fadd2(Bb, Bc), B3);
        TB2 = fadd2(fadd2(Bc, B3), B4);
        TF0 = fadd2(fadd2(Fa, Fb), Fc);
        TF1 = fadd2(fadd2(Fb, Fc), F3);
        TF2 = fadd2(fadd2(Fc, F3), F4);
    }

    // prime the prefetch pipeline
    PREFETCH(r0 + 5);

    float2* pw = (float2*)(pout + (size_t)(gy0 + r0) * WW + (gx0 + 2 * tx));

    #pragma unroll
    for (int s = 0; s < RPT; s++) {
        const u64 S_tl = TA0;                        // rows s..s+2
        const u64 S_bl = TA2;                        // rows s+2..s+4
        const u64 S_lf = fadd2(fadd2(TA0, A3), A4);  // rows s..s+4
        const u64 S_rt = fadd2(fadd2(TB0, B3), B4);
        const u64 S_tp = TF0;
        const u64 S_bt = TF2;
        const u64 xc  = C2;
        const u64 nxc = xc ^ 0x8000000080000000ULL;  // packed negate (exact)

        // channel order: L,R,U,D,NW,NE,SW,SE
        const float2 dL  = asf2(ffma2(S_lf, K15, nxc));
        const float2 dR  = asf2(ffma2(S_rt, K15, nxc));
        const float2 dU  = asf2(ffma2(S_tp, K15, nxc));
        const float2 dD  = asf2(ffma2(S_bt, K15, nxc));
        const float2 dNW = asf2(ffma2(S_tl, K9,  nxc));
        const float2 dNE = asf2(ffma2(S_tl, K81, nxc));
        const float2 dSW = asf2(ffma2(S_bl, K9,  nxc));
        const float2 dSE = asf2(ffma2(S_bl, K81, nxc));
        const float2 xcf = asf2(xc);

        // tournament argmin on |d|; strict '<' keeps lower channel index on ties
        const float a01 = (fabsf(dR.x)  < fabsf(dL.x))  ? dR.x  : dL.x;
        const float a23 = (fabsf(dD.x)  < fabsf(dU.x))  ? dD.x  : dU.x;
        const float a45 = (fabsf(dNE.x) < fabsf(dNW.x)) ? dNE.x : dNW.x;
        const float a67 = (fabsf(dSE.x) < fabsf(dSW.x)) ? dSE.x : dSW.x;
        const float a03 = (fabsf(a23)   < fabsf(a01))   ? a23   : a01;
        const float a47 = (fabsf(a67)   < fabsf(a45))   ? a67   : a45;
        const float best0 = (fabsf(a47) < fabsf(a03))   ? a47   : a03;

        const float b01 = (fabsf(dR.y)  < fabsf(dL.y))  ? dR.y  : dL.y;
        const float b23 = (fabsf(dD.y)  < fabsf(dU.y))  ? dD.y  : dU.y;
        const float b45 = (fabsf(dNE.y) < fabsf(dNW.y)) ? dNE.y : dNW.y;
        const float b67 = (fabsf(dSE.y) < fabsf(dSW.y)) ? dSE.y : dSW.y;
        const float b03 = (fabsf(b23)   < fabsf(b01))   ? b23   : b01;
        const float b47 = (fabsf(b67)   < fabsf(b45))   ? b67   : b45;
        const float best1 = (fabsf(b47) < fabsf(b03))   ? b47   : b03;

        *pw = make_float2(xcf.x + best0, xcf.y + best1);
        pw = (float2*)((float*)pw + WW);

        if (s < RPT - 1) {
            // consume prefetched row s+5, then immediately prefetch row s+6
            u64 An, Bn, Fn, Cn;
            BUILDQ(An, Bn, Fn, Cn);
            if (s < RPT - 2) PREFETCH(r0 + 6 + s);

            TA0 = TA1; TA1 = TA2; TA2 = fadd2(fadd2(A3, A4), An);
            TB0 = TB1; TB1 = TB2; TB2 = fadd2(fadd2(B3, B4), Bn);
            TF0 = TF1; TF1 = TF2; TF2 = fadd2(fadd2(F3, F4), Fn);
            A3 = A4; A4 = An;
            B3 = B4; B4 = Bn;
            F3 = F4; F4 = Fn;
            C2 = C3; C3 = C4; C4 = Cn;
        }
    }
}

extern "C" void kernel_launch(void* const* d_in, const int* in_sizes, int n_in,
                              void* d_out, int out_size)
{
    const float* x = (const float*)d_in[0];
    float* out = (float*)d_out;

    dim3 block(32, 4);
    dim3 grid(WW / TW, HH / TH, NPLANES);

    // iteration = 3 (fixed by setup_inputs)
    swf_step<<<grid, block>>>(x, out, 0, 0);        // x       -> out
    swf_step<<<grid, block>>>(out, nullptr, 0, 1);  // out     -> scratch
    swf_step<<<grid, block>>>(nullptr, out, 1, 0);  // scratch -> out
}

// round 8
// speedup vs baseline: 1.0477x; 1.0477x over previous
#include <cuda_runtime.h>

// SideWindowFilter: 24 planes of 768x768 fp32, r=2, 3 iterations.
// Per pixel: 6 box sums -> 8 directional means -> argmin |mean - x| -> x += d.
// Lean-state variant: B-family (right-3-sums) derived as F - A + C, deleting
// 10 registers of ring state to raise occupancy (reg-limited kernel).

#define HH 768
#define WW 768
#define NPLANES 24
#define TW 64          // tile width
#define TH 64          // tile height
#define RPT 16         // rows per thread; block = (32,4) = 128 threads
#define XS 68          // tile + 2*2 halo

typedef unsigned long long u64;

__device__ float g_scratch[NPLANES * HH * WW];

__device__ __forceinline__ u64 pk(float lo, float hi) {
    u64 r; asm("mov.b64 %0, {%1, %2};" : "=l"(r) : "f"(lo), "f"(hi)); return r;
}
__device__ __forceinline__ u64 fadd2(u64 a, u64 b) {
    u64 r; asm("add.rn.f32x2 %0, %1, %2;" : "=l"(r) : "l"(a), "l"(b)); return r;
}
__device__ __forceinline__ u64 ffma2(u64 a, u64 b, u64 c) {
    u64 r; asm("fma.rn.f32x2 %0, %1, %2, %3;" : "=l"(r) : "l"(a), "l"(b), "l"(c)); return r;
}
__device__ __forceinline__ float2 asf2(u64 v) {
    union { u64 u; float2 f; } cv; cv.u = v; return cv.f;
}
__device__ __forceinline__ u64 asu64(float2 f) {
    union { float2 f; u64 u; } cv; cv.f = f; return cv.u;
}

#define SIGN2 0x8000000080000000ULL

// Build per-row sums for a 2-col window: 3 LDS.64 + 4 packed adds.
//   A = {x0+x1+x2, x1+x2+x3}   (left 3-sum per col)
//   F = {x0..x4,   x1..x5}     (full 5-sum per col)
//   C = {x2, x3}               (centers)
#define ROWBUILD(rr, A, F, C) do {                                      \
    const float2* f2r = (const float2*)xs[rr];                          \
    const float2 p0 = f2r[tx], p1 = f2r[tx + 1], p2 = f2r[tx + 2];      \
    const u64 P0 = asu64(p0), P1 = asu64(p1), P2 = asu64(p2);           \
    const u64 s01 = pk(p0.y, p1.x);                                     \
    const u64 s23 = pk(p1.y, p2.x);                                     \
    const u64 t   = fadd2(s23, P2);                                     \
    A = fadd2(fadd2(P0, s01), P1);                                      \
    F = fadd2(A, t);                                                    \
    C = P1;                                                             \
} while (0)

__global__ __launch_bounds__(128, 10)
void swf_step(const float* __restrict__ in_ext, float* __restrict__ out_ext,
              int in_is_scratch, int out_is_scratch)
{
    __shared__ float xs[XS][XS];   // 18.5 KB

    const float* __restrict__ in  = in_is_scratch  ? (const float*)g_scratch : in_ext;
    float* __restrict__       out = out_is_scratch ? (float*)g_scratch       : out_ext;

    const int plane = blockIdx.z;
    const int gx0 = blockIdx.x * TW;
    const int gy0 = blockIdx.y * TH;
    const float* __restrict__ pin = in  + (size_t)plane * HH * WW;
    float* __restrict__ pout      = out + (size_t)plane * HH * WW;

    const int tx = threadIdx.x;      // 0..31 -> col pair 2*tx
    const int ty = threadIdx.y;      // 0..3  -> row group of 16

    // ---- Phase 1: load 68x68 tile (+halo) ----
    const bool interior = (gx0 >= 2) & (gx0 + XS - 2 <= WW) &
                          (gy0 >= 2) & (gy0 + XS - 2 <= HH);
    if (interior) {
        const float* src0 = pin + (size_t)(gy0 - 2) * WW + (gx0 - 2);
        #pragma unroll
        for (int r = ty; r < XS; r += 4) {
            const float* src = src0 + (size_t)r * WW;
            xs[r][tx]      = __ldg(&src[tx]);
            xs[r][tx + 32] = __ldg(&src[tx + 32]);
            if (tx < XS - TW) xs[r][tx + 64] = __ldg(&src[tx + 64]);
        }
    } else {
        #pragma unroll
        for (int r = ty; r < XS; r += 4) {
            const int gy = gy0 - 2 + r;
            const bool yok = (unsigned)gy < HH;
            const int gxa = gx0 - 2 + tx;
            float v0 = 0.0f, v1 = 0.0f;
            if (yok && (unsigned)gxa < WW)        v0 = __ldg(&pin[(size_t)gy * WW + gxa]);
            xs[r][tx] = v0;
            if (yok && (unsigned)(gxa + 32) < WW) v1 = __ldg(&pin[(size_t)gy * WW + gxa + 32]);
            xs[r][tx + 32] = v1;
            if (tx < XS - TW) {
                float v2 = 0.0f;
                if (yok && (unsigned)(gxa + 64) < WW) v2 = __ldg(&pin[(size_t)gy * WW + gxa + 64]);
                xs[r][tx + 64] = v2;
            }
        }
    }
    __syncthreads();

    const u64 K15 = pk(1.0f / 15.0f, 1.0f / 15.0f);
    const u64 K9  = pk(1.0f / 9.0f,  1.0f / 9.0f);
    const u64 K81 = pk(1.0f / 81.0f, 1.0f / 81.0f);

    const int r0 = ty * RPT;

    // ---- Warm-up: rows r0..r0+4 ----
    // State (15 u64): A3,A4 + TA0..2 | F3,F4 + TF0..2 | C0..C4
    u64 A3, A4, TA0, TA1, TA2;
    u64 F3, F4, TF0, TF1, TF2;
    u64 C0, C1, C2, C3, C4;
    {
        u64 Aa, Ab, Ac, Fa, Fb, Fc;
        ROWBUILD(r0 + 0, Aa, Fa, C0);
        ROWBUILD(r0 + 1, Ab, Fb, C1);
        ROWBUILD(r0 + 2, Ac, Fc, C2);
        ROWBUILD(r0 + 3, A3, F3, C3);
        ROWBUILD(r0 + 4, A4, F4, C4);
        TA0 = fadd2(fadd2(Aa, Ab), Ac);
        TA1 = fadd2(fadd2(Ab, Ac), A3);
        TA2 = fadd2(fadd2(Ac, A3), A4);
        TF0 = fadd2(fadd2(Fa, Fb), Fc);
        TF1 = fadd2(fadd2(Fb, Fc), F3);
        TF2 = fadd2(fadd2(Fc, F3), F4);
    }

    float2* pw = (float2*)(pout + (size_t)(gy0 + r0) * WW + (gx0 + 2 * tx));

    #pragma unroll
    for (int s = 0; s < RPT; s++) {
        const u64 S_tl = TA0;                         // rows s..s+2, left 3 cols
        const u64 S_bl = TA2;                         // rows s+2..s+4
        const u64 S_lf = fadd2(fadd2(TA0, A3), A4);   // 5-row left 3-col sum
        const u64 F5   = fadd2(fadd2(TF0, F3), F4);   // 5-row full 5-col sum
        const u64 C5   = fadd2(fadd2(fadd2(C0, C1), fadd2(C2, C3)), C4);
        const u64 S_rt = fadd2(fadd2(F5, S_lf ^ SIGN2), C5);  // F5 - A5 + C5
        const u64 S_tp = TF0;
        const u64 S_bt = TF2;
        const u64 xc   = C2;
        const u64 nxc  = xc ^ SIGN2;                  // packed negate (exact)

        // channel order: L,R,U,D,NW,NE,SW,SE
        const float2 dL  = asf2(ffma2(S_lf, K15, nxc));
        const float2 dR  = asf2(ffma2(S_rt, K15, nxc));
        const float2 dU  = asf2(ffma2(S_tp, K15, nxc));
        const float2 dD  = asf2(ffma2(S_bt, K15, nxc));
        const float2 dNW = asf2(ffma2(S_tl, K9,  nxc));
        const float2 dNE = asf2(ffma2(S_tl, K81, nxc));
        const float2 dSW = asf2(ffma2(S_bl, K9,  nxc));
        const float2 dSE = asf2(ffma2(S_bl, K81, nxc));
        const float2 xcf = asf2(xc);

        // tournament argmin on |d|; strict '<' keeps lower channel index on ties
        const float a01 = (fabsf(dR.x)  < fabsf(dL.x))  ? dR.x  : dL.x;
        const float a23 = (fabsf(dD.x)  < fabsf(dU.x))  ? dD.x  : dU.x;
        const float a45 = (fabsf(dNE.x) < fabsf(dNW.x)) ? dNE.x : dNW.x;
        const float a67 = (fabsf(dSE.x) < fabsf(dSW.x)) ? dSE.x : dSW.x;
        const float a03 = (fabsf(a23)   < fabsf(a01))   ? a23   : a01;
        const float a47 = (fabsf(a67)   < fabsf(a45))   ? a67   : a45;
        const float best0 = (fabsf(a47) < fabsf(a03))   ? a47   : a03;

        const float b01 = (fabsf(dR.y)  < fabsf(dL.y))  ? dR.y  : dL.y;
        const float b23 = (fabsf(dD.y)  < fabsf(dU.y))  ? dD.y  : dU.y;
        const float b45 = (fabsf(dNE.y) < fabsf(dNW.y)) ? dNE.y : dNW.y;
        const float b67 = (fabsf(dSE.y) < fabsf(dSW.y)) ? dSE.y : dSW.y;
        const float b03 = (fabsf(b23)   < fabsf(b01))   ? b23   : b01;
        const float b47 = (fabsf(b67)   < fabsf(b45))   ? b67   : b45;
        const float best1 = (fabsf(b47) < fabsf(b03))   ? b47   : b03;

        *pw = make_float2(xcf.x + best0, xcf.y + best1);
        pw = (float2*)((float*)pw + WW);

        if (s < RPT - 1) {
            u64 An, Fn, Cn;
            ROWBUILD(r0 + 5 + s, An, Fn, Cn);
            TA0 = TA1; TA1 = TA2; TA2 = fadd2(fadd2(A3, A4), An);
            TF0 = TF1; TF1 = TF2; TF2 = fadd2(fadd2(F3, F4), Fn);
            A3 = A4; A4 = An;
            F3 = F4; F4 = Fn;
            C0 = C1; C1 = C2; C2 = C3; C3 = C4; C4 = Cn;
        }
    }
}

extern "C" void kernel_launch(void* const* d_in, const int* in_sizes, int n_in,
                              void* d_out, int out_size)
{
    const float* x = (const float*)d_in[0];
    float* out = (float*)d_out;

    dim3 block(32, 4);
    dim3 grid(WW / TW, HH / TH, NPLANES);

    // iteration = 3 (fixed by setup_inputs)
    swf_step<<<grid, block>>>(x, out, 0, 0);        // x       -> out
    swf_step<<<grid, block>>>(out, nullptr, 0, 1);  // out     -> scratch
    swf_step<<<grid, block>>>(nullptr, out, 1, 0);  // scratch -> out
}

// round 9
// speedup vs baseline: 1.0964x; 1.0464x over previous
#include <cuda_runtime.h>

// SideWindowFilter: 24 planes of 768x768 fp32, r=2, 3 iterations.
// Per pixel: 6 box sums -> 8 directional means -> argmin |mean - x| -> x += d.
// Lean-state (B-family = F - A + C); short tiles (64x32) for small wave tail;
// reg-capped at 42 for 12 blocks/SM (75% occupancy).

#define HH 768
#define WW 768
#define NPLANES 24
#define TW 64          // tile width
#define TH 32          // tile height
#define RPT 8          // rows per thread; block = (32,4) = 128 threads
#define XS 68          // tile cols + 2*2 halo
#define YS 36          // tile rows + 2*2 halo

typedef unsigned long long u64;

__device__ float g_scratch[NPLANES * HH * WW];

__device__ __forceinline__ u64 pk(float lo, float hi) {
    u64 r; asm("mov.b64 %0, {%1, %2};" : "=l"(r) : "f"(lo), "f"(hi)); return r;
}
__device__ __forceinline__ u64 fadd2(u64 a, u64 b) {
    u64 r; asm("add.rn.f32x2 %0, %1, %2;" : "=l"(r) : "l"(a), "l"(b)); return r;
}
__device__ __forceinline__ u64 ffma2(u64 a, u64 b, u64 c) {
    u64 r; asm("fma.rn.f32x2 %0, %1, %2, %3;" : "=l"(r) : "l"(a), "l"(b), "l"(c)); return r;
}
__device__ __forceinline__ float2 asf2(u64 v) {
    union { u64 u; float2 f; } cv; cv.u = v; return cv.f;
}
__device__ __forceinline__ u64 asu64(float2 f) {
    union { float2 f; u64 u; } cv; cv.f = f; return cv.u;
}

#define SIGN2 0x8000000080000000ULL

// Build per-row sums for a 2-col window: 3 LDS.64 + 4 packed adds.
//   A = {x0+x1+x2, x1+x2+x3}   (left 3-sum per col)
//   F = {x0..x4,   x1..x5}     (full 5-sum per col)
//   C = {x2, x3}               (centers)
#define ROWBUILD(rr, A, F, C) do {                                      \
    const float2* f2r = (const float2*)xs[rr];                          \
    const float2 p0 = f2r[tx], p1 = f2r[tx + 1], p2 = f2r[tx + 2];      \
    const u64 P0 = asu64(p0), P1 = asu64(p1), P2 = asu64(p2);           \
    const u64 s01 = pk(p0.y, p1.x);                                     \
    const u64 s23 = pk(p1.y, p2.x);                                     \
    const u64 t   = fadd2(s23, P2);                                     \
    A = fadd2(fadd2(P0, s01), P1);                                      \
    F = fadd2(A, t);                                                    \
    C = P1;                                                             \
} while (0)

__global__ __launch_bounds__(128, 12)
void swf_step(const float* __restrict__ in_ext, float* __restrict__ out_ext,
              int in_is_scratch, int out_is_scratch)
{
    __shared__ float xs[YS][XS];   // 9.6 KB

    const float* __restrict__ in  = in_is_scratch  ? (const float*)g_scratch : in_ext;
    float* __restrict__       out = out_is_scratch ? (float*)g_scratch       : out_ext;

    const int plane = blockIdx.z;
    const int gx0 = blockIdx.x * TW;
    const int gy0 = blockIdx.y * TH;
    const float* __restrict__ pin = in  + (size_t)plane * HH * WW;
    float* __restrict__ pout      = out + (size_t)plane * HH * WW;

    const int tx = threadIdx.x;      // 0..31 -> col pair 2*tx
    const int ty = threadIdx.y;      // 0..3  -> row group of 8

    // ---- Phase 1: load 36x68 tile (+halo) ----
    const bool interior = (gx0 >= 2) & (gx0 + XS - 2 <= WW) &
                          (gy0 >= 2) & (gy0 + YS - 2 <= HH);
    if (interior) {
        const float* src0 = pin + (size_t)(gy0 - 2) * WW + (gx0 - 2);
        #pragma unroll
        for (int r = ty; r < YS; r += 4) {
            const float* src = src0 + (size_t)r * WW;
            xs[r][tx]      = __ldg(&src[tx]);
            xs[r][tx + 32] = __ldg(&src[tx + 32]);
            if (tx < XS - TW) xs[r][tx + 64] = __ldg(&src[tx + 64]);
        }
    } else {
        #pragma unroll
        for (int r = ty; r < YS; r += 4) {
            const int gy = gy0 - 2 + r;
            const bool yok = (unsigned)gy < HH;
            const int gxa = gx0 - 2 + tx;
            float v0 = 0.0f, v1 = 0.0f;
            if (yok && (unsigned)gxa < WW)        v0 = __ldg(&pin[(size_t)gy * WW + gxa]);
            xs[r][tx] = v0;
            if (yok && (unsigned)(gxa + 32) < WW) v1 = __ldg(&pin[(size_t)gy * WW + gxa + 32]);
            xs[r][tx + 32] = v1;
            if (tx < XS - TW) {
                float v2 = 0.0f;
                if (yok && (unsigned)(gxa + 64) < WW) v2 = __ldg(&pin[(size_t)gy * WW + gxa + 64]);
                xs[r][tx + 64] = v2;
            }
        }
    }
    __syncthreads();

    const u64 K15 = pk(1.0f / 15.0f, 1.0f / 15.0f);
    const u64 K9  = pk(1.0f / 9.0f,  1.0f / 9.0f);
    const u64 K81 = pk(1.0f / 81.0f, 1.0f / 81.0f);

    const int r0 = ty * RPT;

    // ---- Warm-up: rows r0..r0+4 ----
    // State (15 u64): A3,A4 + TA0..2 | F3,F4 + TF0..2 | C0..C4
    u64 A3, A4, TA0, TA1, TA2;
    u64 F3, F4, TF0, TF1, TF2;
    u64 C0, C1, C2, C3, C4;
    {
        u64 Aa, Ab, Ac, Fa, Fb, Fc;
        ROWBUILD(r0 + 0, Aa, Fa, C0);
        ROWBUILD(r0 + 1, Ab, Fb, C1);
        ROWBUILD(r0 + 2, Ac, Fc, C2);
        ROWBUILD(r0 + 3, A3, F3, C3);
        ROWBUILD(r0 + 4, A4, F4, C4);
        TA0 = fadd2(fadd2(Aa, Ab), Ac);
        TA1 = fadd2(fadd2(Ab, Ac), A3);
        TA2 = fadd2(fadd2(Ac, A3), A4);
        TF0 = fadd2(fadd2(Fa, Fb), Fc);
        TF1 = fadd2(fadd2(Fb, Fc), F3);
        TF2 = fadd2(fadd2(Fc, F3), F4);
    }

    float2* pw = (float2*)(pout + (size_t)(gy0 + r0) * WW + (gx0 + 2 * tx));

    #pragma unroll
    for (int s = 0; s < RPT; s++) {
        const u64 S_tl = TA0;                         // rows s..s+2, left 3 cols
        const u64 S_bl = TA2;                         // rows s+2..s+4
        const u64 S_lf = fadd2(fadd2(TA0, A3), A4);   // 5-row left 3-col sum
        const u64 F5   = fadd2(fadd2(TF0, F3), F4);   // 5-row full 5-col sum
        const u64 C5   = fadd2(fadd2(fadd2(C0, C1), fadd2(C2, C3)), C4);
        const u64 S_rt = fadd2(fadd2(F5, S_lf ^ SIGN2), C5);  // F5 - A5 + C5
        const u64 S_tp = TF0;
        const u64 S_bt = TF2;
        const u64 xc   = C2;
        const u64 nxc  = xc ^ SIGN2;                  // packed negate (exact)

        // channel order: L,R,U,D,NW,NE,SW,SE
        const float2 dL  = asf2(ffma2(S_lf, K15, nxc));
        const float2 dR  = asf2(ffma2(S_rt, K15, nxc));
        const float2 dU  = asf2(ffma2(S_tp, K15, nxc));
        const float2 dD  = asf2(ffma2(S_bt, K15, nxc));
        const float2 dNW = asf2(ffma2(S_tl, K9,  nxc));
        const float2 dNE = asf2(ffma2(S_tl, K81, nxc));
        const float2 dSW = asf2(ffma2(S_bl, K9,  nxc));
        const float2 dSE = asf2(ffma2(S_bl, K81, nxc));
        const float2 xcf = asf2(xc);

        // tournament argmin on |d|; strict '<' keeps lower channel index on ties
        const float a01 = (fabsf(dR.x)  < fabsf(dL.x))  ? dR.x  : dL.x;
        const float a23 = (fabsf(dD.x)  < fabsf(dU.x))  ? dD.x  : dU.x;
        const float a45 = (fabsf(dNE.x) < fabsf(dNW.x)) ? dNE.x : dNW.x;
        const float a67 = (fabsf(dSE.x) < fabsf(dSW.x)) ? dSE.x : dSW.x;
        const float a03 = (fabsf(a23)   < fabsf(a01))   ? a23   : a01;
        const float a47 = (fabsf(a67)   < fabsf(a45))   ? a67   : a45;
        const float best0 = (fabsf(a47) < fabsf(a03))   ? a47   : a03;

        const float b01 = (fabsf(dR.y)  < fabsf(dL.y))  ? dR.y  : dL.y;
        const float b23 = (fabsf(dD.y)  < fabsf(dU.y))  ? dD.y  : dU.y;
        const float b45 = (fabsf(dNE.y) < fabsf(dNW.y)) ? dNE.y : dNW.y;
        const float b67 = (fabsf(dSE.y) < fabsf(dSW.y)) ? dSE.y : dSW.y;
        const float b03 = (fabsf(b23)   < fabsf(b01))   ? b23   : b01;
        const float b47 = (fabsf(b67)   < fabsf(b45))   ? b67   : b45;
        const float best1 = (fabsf(b47) < fabsf(b03))   ? b47   : b03;

        *pw = make_float2(xcf.x + best0, xcf.y + best1);
        pw = (float2*)((float*)pw + WW);

        if (s < RPT - 1) {
            u64 An, Fn, Cn;
            ROWBUILD(r0 + 5 + s, An, Fn, Cn);
            TA0 = TA1; TA1 = TA2; TA2 = fadd2(fadd2(A3, A4), An);
            TF0 = TF1; TF1 = TF2; TF2 = fadd2(fadd2(F3, F4), Fn);
            A3 = A4; A4 = An;
            F3 = F4; F4 = Fn;
            C0 = C1; C1 = C2; C2 = C3; C3 = C4; C4 = Cn;
        }
    }
}

extern "C" void kernel_launch(void* const* d_in, const int* in_sizes, int n_in,
                              void* d_out, int out_size)
{
    const float* x = (const float*)d_in[0];
    float* out = (float*)d_out;

    dim3 block(32, 4);
    dim3 grid(WW / TW, HH / TH, NPLANES);

    // iteration = 3 (fixed by setup_inputs)
    swf_step<<<grid, block>>>(x, out, 0, 0);        // x       -> out
    swf_step<<<grid, block>>>(out, nullptr, 0, 1);  // out     -> scratch
    swf_step<<<grid, block>>>(nullptr, out, 1, 0);  // scratch -> out
}